// round 14
// baseline (speedup 1.0000x reference)
#include <cuda_runtime.h>
#include <cuda_fp16.h>
#include <math.h>
#include <stdint.h>

#define TOK   8192
#define HD    1024
#define FD    4096
#define ED    8
#define NJOBS (TOK * 2)
#define MAXBLK 136

// ---------------- device scratch ----------------
__device__ __half g_xhi[(size_t)TOK * HD];
__device__ __half g_w1hi[(size_t)ED * HD * FD];
__device__ __half g_w2hi[(size_t)ED * FD * HD];
__device__ __half g_hh[(size_t)NJOBS * FD];
__device__ float  g_obuf[(size_t)2 * NJOBS * HD];   // two K-split partials for GEMM2
__device__ int    g_jobs_tok[NJOBS];
__device__ int    g_jobs_e[NJOBS];
__device__ float  g_jobs_p[NJOBS];
__device__ int    g_cnt[ED];
__device__ int    g_off[ED];
__device__ int    g_topk_e[NJOBS];
__device__ float  g_topk_p[NJOBS];
__device__ int    g_blk_e[MAXBLK];
__device__ int    g_blk_m[MAXBLK];
__device__ int    g_nblk;

// ---------------- PTX helpers (sm_80-class only) ----------------
__device__ __forceinline__ uint32_t smem_u32(const void* p) {
    uint32_t a;
    asm("{ .reg .u64 t; cvta.to.shared.u64 t, %1; cvt.u32.u64 %0, t; }" : "=r"(a) : "l"(p));
    return a;
}
__device__ __forceinline__ void ldsm_x4(uint32_t* r, uint32_t addr) {
    asm volatile("ldmatrix.sync.aligned.m8n8.x4.shared.b16 {%0,%1,%2,%3}, [%4];"
        : "=r"(r[0]), "=r"(r[1]), "=r"(r[2]), "=r"(r[3]) : "r"(addr));
}
__device__ __forceinline__ void ldsm_x4_t(uint32_t* r, uint32_t addr) {
    asm volatile("ldmatrix.sync.aligned.m8n8.x4.trans.shared.b16 {%0,%1,%2,%3}, [%4];"
        : "=r"(r[0]), "=r"(r[1]), "=r"(r[2]), "=r"(r[3]) : "r"(addr));
}
__device__ __forceinline__ void mma16816(float* d, const uint32_t* a, const uint32_t* b) {
    asm volatile("mma.sync.aligned.m16n8k16.row.col.f32.f16.f16.f32 "
        "{%0,%1,%2,%3}, {%4,%5,%6,%7}, {%8,%9}, {%0,%1,%2,%3};"
        : "+f"(d[0]), "+f"(d[1]), "+f"(d[2]), "+f"(d[3])
        : "r"(a[0]), "r"(a[1]), "r"(a[2]), "r"(a[3]), "r"(b[0]), "r"(b[1]));
}
__device__ __forceinline__ void cp16(uint32_t dst, const void* src) {
    asm volatile("cp.async.cg.shared.global [%0], [%1], 16;"
        :: "r"(dst), "l"(__cvta_generic_to_global(src)) : "memory");
}
#define CP_COMMIT() asm volatile("cp.async.commit_group;" ::: "memory")
#define CP_WAIT(n)  asm volatile("cp.async.wait_group %0;" :: "n"(n) : "memory")

// ---------------- reductions ----------------
__device__ __forceinline__ float block_reduce_sum(float v, float* red) {
    int tid = threadIdx.x;
    red[tid] = v;
    __syncthreads();
#pragma unroll
    for (int o = 128; o > 0; o >>= 1) {
        if (tid < o) red[tid] += red[tid + o];
        __syncthreads();
    }
    float r = red[0];
    __syncthreads();
    return r;
}

// ---------------- kernel 0: gating ----------------
__global__ void gate_kernel(const float* __restrict__ x,
                            const float* __restrict__ gn_g,
                            const float* __restrict__ gn_b,
                            const float* __restrict__ gate_w,
                            const float* __restrict__ gate_b) {
    int t = blockIdx.x, tid = threadIdx.x;
    const float4* xr4 = (const float4*)(x + (size_t)t * HD);
    __shared__ float red[256];
    __shared__ float sm_mean, sm_rstd;
    __shared__ float sm_logits[ED];

    float4 xv = xr4[tid];
    float xs[4] = {xv.x, xv.y, xv.z, xv.w};
    float s = 0.f, s2 = 0.f;
#pragma unroll
    for (int i = 0; i < 4; i++) { s += xs[i]; s2 += xs[i] * xs[i]; }
    float tot = block_reduce_sum(s, red);
    if (tid == 0) sm_mean = tot * (1.f / HD);
    float tot2 = block_reduce_sum(s2, red);
    if (tid == 0) {
        float m = sm_mean;
        sm_rstd = rsqrtf(tot2 * (1.f / HD) - m * m + 1e-5f);
    }
    __syncthreads();
    float m = sm_mean, r = sm_rstd;
    float acc[ED];
#pragma unroll
    for (int e = 0; e < ED; e++) acc[e] = 0.f;
#pragma unroll
    for (int i = 0; i < 4; i++) {
        int h = tid * 4 + i;
        float xn = (xs[i] - m) * r * gn_g[h] + gn_b[h];
#pragma unroll
        for (int e = 0; e < ED; e++) acc[e] += xn * gate_w[h * ED + e];
    }
#pragma unroll
    for (int e = 0; e < ED; e++) {
        float le = block_reduce_sum(acc[e], red);
        if (tid == 0) sm_logits[e] = le + gate_b[e];
    }
    __syncthreads();
    if (tid == 0) {
        float l[ED], pr[ED];
        float mx = -1e30f;
#pragma unroll
        for (int e = 0; e < ED; e++) { l[e] = sm_logits[e]; mx = fmaxf(mx, l[e]); }
        float ssum = 0.f;
#pragma unroll
        for (int e = 0; e < ED; e++) { pr[e] = expf(l[e] - mx); ssum += pr[e]; }
        float inv = 1.f / ssum;
#pragma unroll
        for (int e = 0; e < ED; e++) pr[e] *= inv;
        int i0 = 0;
#pragma unroll
        for (int e = 1; e < ED; e++) if (pr[e] > pr[i0]) i0 = e;
        int i1 = (i0 == 0) ? 1 : 0;
#pragma unroll
        for (int e = 0; e < ED; e++) if (e != i0 && pr[e] > pr[i1]) i1 = e;
        float p0 = pr[i0], p1 = pr[i1];
        float dn = 1.f / (p0 + p1 + 1e-9f);
        g_topk_e[t * 2 + 0] = i0;  g_topk_p[t * 2 + 0] = p0 * dn;
        g_topk_e[t * 2 + 1] = i1;  g_topk_p[t * 2 + 1] = p1 * dn;
    }
}

// ---------------- kernel 1: finalize routing + block list (1 block) ----------------
__global__ void __launch_bounds__(1024) finalize_kernel() {
    __shared__ int scnt[ED], soff[ED], sfill[ED];
    int tid = threadIdx.x;
    if (tid < ED) { scnt[tid] = 0; sfill[tid] = 0; }
    __syncthreads();
    for (int j = tid; j < NJOBS; j += 1024) atomicAdd(&scnt[g_topk_e[j]], 1);
    __syncthreads();
    if (tid == 0) {
        int o = 0, nb = 0;
        for (int e = 0; e < ED; e++) {
            soff[e] = o;
            g_off[e] = o;
            g_cnt[e] = scnt[e];
            for (int mm = 0; mm < scnt[e]; mm += 128) {
                g_blk_e[nb] = e;
                g_blk_m[nb] = mm;
                nb++;
            }
            o += scnt[e];
        }
        g_nblk = nb;
    }
    __syncthreads();
    for (int j = tid; j < NJOBS; j += 1024) {
        int e = g_topk_e[j];
        int pos = atomicAdd(&sfill[e], 1);
        int jj = soff[e] + pos;
        g_jobs_tok[jj] = j >> 1;
        g_jobs_e[jj]   = e;
        g_jobs_p[jj]   = g_topk_p[j];
    }
}

// ---------------- kernel 2: all converts in one launch (hi planes only) ----------------
#define NX4  ((size_t)TOK * HD / 4)
#define NW4  ((size_t)ED * HD * FD / 4)
__global__ void __launch_bounds__(256) convert_all(const float* __restrict__ x,
                                                   const float* __restrict__ W1,
                                                   const float* __restrict__ W2) {
    size_t i = (size_t)blockIdx.x * 256 + threadIdx.x;
    if (i >= NX4 + 2 * NW4) return;
    const float4* src;
    __half* dst;
    size_t jj;
    if (i < NX4) { src = (const float4*)x; dst = g_xhi; jj = i; }
    else if (i < NX4 + NW4) { src = (const float4*)W1; dst = g_w1hi; jj = i - NX4; }
    else { src = (const float4*)W2; dst = g_w2hi; jj = i - NX4 - NW4; }
    float4 v = src[jj];
    uint32_t hw[2];
    __half h0 = __float2half_rn(v.x), h1 = __float2half_rn(v.y);
    __half h2 = __float2half_rn(v.z), h3 = __float2half_rn(v.w);
    hw[0] = (uint32_t)__half_as_ushort(h0) | ((uint32_t)__half_as_ushort(h1) << 16);
    hw[1] = (uint32_t)__half_as_ushort(h2) | ((uint32_t)__half_as_ushort(h3) << 16);
    ((uint2*)dst)[jj] = make_uint2(hw[0], hw[1]);
}

// ---------------- 1-pass fp16 grouped GEMM, 128m x 256n x 64k, 256 threads ----------------
// 8 warps = 2m x 4n; warp tile 64m x 64n; acc 128 floats/thread (255-reg budget).
// Register-level fragment double-buffering: every (jj,g) step prefetches the next
// step's B fragment (and A fragments at jj boundaries) before issuing its 8 MMAs.
// Stage = A 16KB (128 rows x 128B) + B 32KB (64 k-rows x 512B); 4 stages = 192KB.
#define STAGES 4
#define STAGE_BYTES 49152
#define SMEM_BYTES (1024 + STAGES * STAGE_BYTES)
#define GTHREADS 256

template <int KDIM, int NDIM, int KSPLIT, bool GATHER, bool DOGELU>
__global__ void __launch_bounds__(GTHREADS, 1)
gemm_mma(const __half* __restrict__ Ahi,  // [rows][KDIM]
         const __half* __restrict__ Whi,  // [E][KDIM][NDIM]
         const float* __restrict__ bias) {
    if ((int)blockIdx.x >= g_nblk) return;
    int e   = g_blk_e[blockIdx.x];
    int m0  = g_blk_m[blockIdx.x];
    int cnt = g_cnt[e];
    int off = g_off[e];
    constexpr int NB = NDIM / 256;
    int ky = blockIdx.y / NB;
    int n0 = (blockIdx.y % NB) * 256;
    constexpr int KSEG = KDIM / KSPLIT;
    int k0g = ky * KSEG;

    extern __shared__ __align__(1024) char smem[];
    uint32_t sb = smem_u32(smem);
    int tid = threadIdx.x, wid = tid >> 5, lane = tid & 31;
    int wm = wid >> 2, wn = wid & 3;   // 2m x 4n warp grid, warp tile 64x64
    int* s_tok = (int*)smem;

    if (GATHER && tid < 128) {
        int r = (m0 + tid < cnt) ? tid : 0;
        s_tok[tid] = g_jobs_tok[off + m0 + r];
    }
    __syncthreads();

    const __half* We_hi = Whi + (size_t)e * KDIM * NDIM + (size_t)k0g * NDIM + n0;
    const float* be = bias + (size_t)e * NDIM;

    // ---- A producer: 4 chunks/thread (r = tid>>3 + q*32; kg = tid&7).
    int akg = tid & 7;
    uint32_t aswz = 16u * (uint32_t)(akg ^ ((tid >> 3) & 7));   // r&7 q-invariant (stride 32)
    int acol = akg * 8 + k0g;
    const __half* asrc[4];
    uint32_t adst[4];
#pragma unroll
    for (int q = 0; q < 4; q++) {
        int r = (tid >> 3) + q * 32;
        int row;
        if (GATHER) row = s_tok[r];
        else { int rr = (m0 + r < cnt) ? r : 0; row = off + m0 + rr; }
        asrc[q] = Ahi + (size_t)row * KDIM + acol;
        adst[q] = (uint32_t)(r * 128) + aswz;
    }
    // ---- B producer: 8 chunks/thread (kr = tid>>5 + q*8; u = tid&31).
    int bu = tid & 31, bk0 = tid >> 5;
    uint32_t bswz = (uint32_t)((bu >> 3) * 128 + 16 * ((bu & 7) ^ (bk0 & 7)));  // kr&7 q-invariant
    const __half* bsrc_hi = We_hi + (size_t)bk0 * NDIM + bu * 8;

    auto issue = [&](int s, int it) {
        uint32_t base = sb + 1024 + s * STAGE_BYTES;
#pragma unroll
        for (int q = 0; q < 4; q++) cp16(base + adst[q], asrc[q] + it * 64);
        uint32_t bb = base + 16384;
        size_t koff = (size_t)it * 64 * NDIM;
#pragma unroll
        for (int q = 0; q < 8; q++)
            cp16(bb + (uint32_t)((bk0 + q * 8) * 512) + bswz,
                 bsrc_hi + koff + (size_t)(q * 8) * NDIM);
    };

    float acc[32][4];
#pragma unroll
    for (int i = 0; i < 32; i++)
#pragma unroll
        for (int j = 0; j < 4; j++) acc[i][j] = 0.f;

    constexpr int KIT = KSEG / 64;
#pragma unroll
    for (int s = 0; s < STAGES - 1; s++) {
        if (s < KIT) issue(s, s);
        CP_COMMIT();
    }

    int rl = lane & 15, cg = lane >> 4;
    uint32_t afr[2][4][4];   // double-buffered A fragments (per jj parity)
    uint32_t bfr[2][4];      // double-buffered B fragment (per step parity)

    for (int it = 0; it < KIT; it++) {
        CP_WAIT(STAGES - 2);
        __syncthreads();
        uint32_t As = sb + 1024 + (it % STAGES) * STAGE_BYTES;
        uint32_t Bs = As + 16384;

        // initial fragments for (jj=0, g=0)
#pragma unroll
        for (int mt = 0; mt < 4; mt++) {
            int r = wm * 64 + mt * 16 + rl;
            ldsm_x4(afr[0][mt], As + r * 128 + 16 * ((0 * 2 + cg) ^ (r & 7)));
        }
        {
            int rB = rl;
            ldsm_x4_t(bfr[0], Bs + rB * 512 + wn * 128 + 16 * ((0 * 2 + cg) ^ (rB & 7)));
        }

#pragma unroll
        for (int step = 0; step < 16; step++) {
            int jj = step >> 2, g = step & 3;
            int cur = step & 1;
            // prefetch next step's fragments
            if (step < 15) {
                int sn = step + 1;
                int jn = sn >> 2, gn = sn & 3;
                if (gn == 0) {
#pragma unroll
                    for (int mt = 0; mt < 4; mt++) {
                        int r = wm * 64 + mt * 16 + rl;
                        ldsm_x4(afr[jn & 1][mt],
                                As + r * 128 + 16 * ((jn * 2 + cg) ^ (r & 7)));
                    }
                }
                int rB = jn * 16 + rl;
                ldsm_x4_t(bfr[cur ^ 1],
                          Bs + rB * 512 + wn * 128 + 16 * ((gn * 2 + cg) ^ (rB & 7)));
            }
            int ab = jj & 1;
#pragma unroll
            for (int mt = 0; mt < 4; mt++)
#pragma unroll
                for (int hh = 0; hh < 2; hh++)
                    mma16816(acc[mt * 8 + g * 2 + hh], afr[ab][mt], &bfr[cur][hh * 2]);
        }
        int nxt = it + STAGES - 1;
        if (nxt < KIT) issue(nxt % STAGES, nxt);
        CP_COMMIT();
    }

    // ---- epilogue ----
#pragma unroll
    for (int mt = 0; mt < 4; mt++) {
#pragma unroll
        for (int nt = 0; nt < 8; nt++) {
            float* d = acc[mt * 8 + nt];
            int nc = n0 + wn * 64 + nt * 8 + 2 * (lane & 3);
            int r0 = m0 + wm * 64 + mt * 16 + (lane >> 2);
            int r1 = r0 + 8;
            if (DOGELU) {
                float b0 = be[nc], b1 = be[nc + 1];
                float c00 = d[0] + b0, c01 = d[1] + b1;
                float c10 = d[2] + b0, c11 = d[3] + b1;
                c00 = 0.5f * c00 * (1.f + erff(c00 * 0.70710678118654752f));
                c01 = 0.5f * c01 * (1.f + erff(c01 * 0.70710678118654752f));
                c10 = 0.5f * c10 * (1.f + erff(c10 * 0.70710678118654752f));
                c11 = 0.5f * c11 * (1.f + erff(c11 * 0.70710678118654752f));
                auto wr = [&](int rr, float a, float b) {
                    size_t base = (size_t)(off + rr) * NDIM + nc;
                    __half h0 = __float2half_rn(a), h1 = __float2half_rn(b);
                    *(uint32_t*)(g_hh + base) =
                        (uint32_t)__half_as_ushort(h0) | ((uint32_t)__half_as_ushort(h1) << 16);
                };
                if (r0 < cnt) wr(r0, c00, c01);
                if (r1 < cnt) wr(r1, c10, c11);
            } else {
                // partial (no bias; bias + sum in combine)
                float* ob = g_obuf + (size_t)ky * NJOBS * HD;
                if (r0 < cnt) *(float2*)(ob + (size_t)(off + r0) * NDIM + nc) = make_float2(d[0], d[1]);
                if (r1 < cnt) *(float2*)(ob + (size_t)(off + r1) * NDIM + nc) = make_float2(d[2], d[3]);
            }
        }
    }
}

// ---------------- combine: LN(o0 + o1 + b2 + residual) * p ----------------
__global__ void combine_kernel(const float* __restrict__ x,
                               const float* __restrict__ b2,
                               const float* __restrict__ ln_g,
                               const float* __restrict__ ln_b,
                               float* __restrict__ y) {
    int j = blockIdx.x, tid = threadIdx.x;
    int t = g_jobs_tok[j];
    int e = g_jobs_e[j];
    float p = g_jobs_p[j];
    const float4* o0 = (const float4*)(g_obuf + (size_t)j * HD);
    const float4* o1 = (const float4*)(g_obuf + (size_t)(NJOBS + j) * HD);
    const float4* xrow = (const float4*)(x + (size_t)t * HD);
    const float4* brow = (const float4*)(b2 + (size_t)e * HD);
    __shared__ float red[256];
    __shared__ float sm_mean, sm_rstd;
    float4 a = o0[tid], b = o1[tid], xv = xrow[tid], bb = brow[tid];
    float v[4] = {a.x + b.x + bb.x + xv.x, a.y + b.y + bb.y + xv.y,
                  a.z + b.z + bb.z + xv.z, a.w + b.w + bb.w + xv.w};
    float s = 0.f, s2 = 0.f;
#pragma unroll
    for (int i = 0; i < 4; i++) { s += v[i]; s2 += v[i] * v[i]; }
    float tot = block_reduce_sum(s, red);
    if (tid == 0) sm_mean = tot * (1.f / HD);
    float tot2 = block_reduce_sum(s2, red);
    if (tid == 0) {
        float m = sm_mean;
        sm_rstd = rsqrtf(tot2 * (1.f / HD) - m * m + 1e-5f);
    }
    __syncthreads();
    float m = sm_mean, r = sm_rstd;
#pragma unroll
    for (int i = 0; i < 4; i++) {
        int h = tid * 4 + i;
        float o = (v[i] - m) * r * ln_g[(size_t)e * HD + h] + ln_b[(size_t)e * HD + h];
        atomicAdd(&y[(size_t)t * HD + h], o * p);
    }
}

// ---------------- launch ----------------
extern "C" void kernel_launch(void* const* d_in, const int* in_sizes, int n_in,
                              void* d_out, int out_size) {
    const float* x      = (const float*)d_in[0];
    const float* W1     = (const float*)d_in[1];
    const float* b1     = (const float*)d_in[2];
    const float* W2     = (const float*)d_in[3];
    const float* b2     = (const float*)d_in[4];
    const float* ln_g   = (const float*)d_in[5];
    const float* ln_b   = (const float*)d_in[6];
    const float* gn_g   = (const float*)d_in[7];
    const float* gn_b   = (const float*)d_in[8];
    const float* gate_w = (const float*)d_in[9];
    const float* gate_b = (const float*)d_in[10];
    float* y = (float*)d_out;

    __half *xhi, *w1hi, *w2hi, *hh;
    cudaGetSymbolAddress((void**)&xhi,  g_xhi);
    cudaGetSymbolAddress((void**)&w1hi, g_w1hi);
    cudaGetSymbolAddress((void**)&w2hi, g_w2hi);
    cudaGetSymbolAddress((void**)&hh,   g_hh);

    cudaFuncSetAttribute(gemm_mma<HD, FD, 1, true, true>,
                         cudaFuncAttributeMaxDynamicSharedMemorySize, SMEM_BYTES);
    cudaFuncSetAttribute(gemm_mma<FD, HD, 2, false, false>,
                         cudaFuncAttributeMaxDynamicSharedMemorySize, SMEM_BYTES);

    // 0: gating; 1: routing finalize; 2: converts; 3: GEMM1 (ncu slot)
    gate_kernel<<<TOK, 256>>>(x, gn_g, gn_b, gate_w, gate_b);
    finalize_kernel<<<1, 1024>>>();
    {
        size_t total = NX4 + 2 * NW4;
        convert_all<<<(unsigned)((total + 255) / 256), 256>>>(x, W1, W2);
    }
    // GEMM1: h = gelu(x @ W1[e] + b1[e]); K=1024 (16 k-iters), N=4096
    gemm_mma<HD, FD, 1, true, true>
        <<<dim3(MAXBLK, FD / 256), GTHREADS, SMEM_BYTES>>>(xhi, w1hi, b1);
    // GEMM2: partials = h @ W2[e]; K=4096 split x2 (32 k-iters each), N=1024
    gemm_mma<FD, HD, 2, false, false>
        <<<dim3(MAXBLK, (HD / 256) * 2), GTHREADS, SMEM_BYTES>>>(hh, w2hi, b2);

    cudaMemsetAsync(d_out, 0, (size_t)out_size * sizeof(float), 0);
    combine_kernel<<<NJOBS, 256>>>(x, b2, ln_g, ln_b, y);
}

// round 15
// speedup vs baseline: 1.0937x; 1.0937x over previous
#include <cuda_runtime.h>
#include <cuda_fp16.h>
#include <math.h>
#include <stdint.h>

#define TOK   8192
#define HD    1024
#define FD    4096
#define ED    8
#define NJOBS (TOK * 2)
#define MAXBLK 136

// ---------------- device scratch ----------------
__device__ __half g_xhi[(size_t)TOK * HD];
__device__ __half g_w1hi[(size_t)ED * HD * FD];
__device__ __half g_w2hi[(size_t)ED * FD * HD];
__device__ __half g_hh[(size_t)NJOBS * FD];
__device__ float  g_obuf[(size_t)2 * NJOBS * HD];   // two K-split partials for GEMM2
__device__ int    g_jobs_tok[NJOBS];
__device__ int    g_tok2job[NJOBS];
__device__ int    g_cnt[ED];
__device__ int    g_off[ED];
__device__ int    g_topk_e[NJOBS];
__device__ float  g_topk_p[NJOBS];
__device__ int    g_blk_e[MAXBLK];
__device__ int    g_blk_m[MAXBLK];
__device__ int    g_nblk;

// ---------------- PTX helpers (sm_80-class only) ----------------
__device__ __forceinline__ uint32_t smem_u32(const void* p) {
    uint32_t a;
    asm("{ .reg .u64 t; cvta.to.shared.u64 t, %1; cvt.u32.u64 %0, t; }" : "=r"(a) : "l"(p));
    return a;
}
__device__ __forceinline__ void ldsm_x4(uint32_t* r, uint32_t addr) {
    asm volatile("ldmatrix.sync.aligned.m8n8.x4.shared.b16 {%0,%1,%2,%3}, [%4];"
        : "=r"(r[0]), "=r"(r[1]), "=r"(r[2]), "=r"(r[3]) : "r"(addr));
}
__device__ __forceinline__ void ldsm_x4_t(uint32_t* r, uint32_t addr) {
    asm volatile("ldmatrix.sync.aligned.m8n8.x4.trans.shared.b16 {%0,%1,%2,%3}, [%4];"
        : "=r"(r[0]), "=r"(r[1]), "=r"(r[2]), "=r"(r[3]) : "r"(addr));
}
__device__ __forceinline__ void mma16816(float* d, const uint32_t* a, const uint32_t* b) {
    asm volatile("mma.sync.aligned.m16n8k16.row.col.f32.f16.f16.f32 "
        "{%0,%1,%2,%3}, {%4,%5,%6,%7}, {%8,%9}, {%0,%1,%2,%3};"
        : "+f"(d[0]), "+f"(d[1]), "+f"(d[2]), "+f"(d[3])
        : "r"(a[0]), "r"(a[1]), "r"(a[2]), "r"(a[3]), "r"(b[0]), "r"(b[1]));
}
__device__ __forceinline__ void cp16(uint32_t dst, const void* src) {
    asm volatile("cp.async.cg.shared.global [%0], [%1], 16;"
        :: "r"(dst), "l"(__cvta_generic_to_global(src)) : "memory");
}
#define CP_COMMIT() asm volatile("cp.async.commit_group;" ::: "memory")
#define CP_WAIT(n)  asm volatile("cp.async.wait_group %0;" :: "n"(n) : "memory")

// ---------------- kernel 0: gating (shuffle reductions, 4 barriers) ----------------
__global__ void gate_kernel(const float* __restrict__ x,
                            const float* __restrict__ gn_g,
                            const float* __restrict__ gn_b,
                            const float* __restrict__ gate_w,
                            const float* __restrict__ gate_b) {
    int t = blockIdx.x, tid = threadIdx.x;
    int lane = tid & 31, wid = tid >> 5;   // 8 warps
    const float4* xr4 = (const float4*)(x + (size_t)t * HD);

    __shared__ float ws[8], ws2[8];
    __shared__ float wl[8][8];
    __shared__ float sm_mean, sm_rstd;
    __shared__ float sm_logits[ED];

    float4 xv = xr4[tid];
    float xs[4] = {xv.x, xv.y, xv.z, xv.w};
    float s = 0.f, s2 = 0.f;
#pragma unroll
    for (int i = 0; i < 4; i++) { s += xs[i]; s2 += xs[i] * xs[i]; }
#pragma unroll
    for (int o = 16; o > 0; o >>= 1) {
        s  += __shfl_xor_sync(0xFFFFFFFFu, s,  o);
        s2 += __shfl_xor_sync(0xFFFFFFFFu, s2, o);
    }
    if (lane == 0) { ws[wid] = s; ws2[wid] = s2; }
    __syncthreads();
    if (tid == 0) {
        float ts = 0.f, ts2 = 0.f;
#pragma unroll
        for (int w = 0; w < 8; w++) { ts += ws[w]; ts2 += ws2[w]; }
        float m = ts * (1.f / HD);
        sm_mean = m;
        sm_rstd = rsqrtf(ts2 * (1.f / HD) - m * m + 1e-5f);
    }
    __syncthreads();

    float m = sm_mean, r = sm_rstd;
    float acc[ED];
#pragma unroll
    for (int e = 0; e < ED; e++) acc[e] = 0.f;
#pragma unroll
    for (int i = 0; i < 4; i++) {
        int h = tid * 4 + i;
        float xn = (xs[i] - m) * r * gn_g[h] + gn_b[h];
#pragma unroll
        for (int e = 0; e < ED; e++) acc[e] += xn * gate_w[h * ED + e];
    }
#pragma unroll
    for (int e = 0; e < ED; e++)
#pragma unroll
        for (int o = 16; o > 0; o >>= 1)
            acc[e] += __shfl_xor_sync(0xFFFFFFFFu, acc[e], o);
    if (lane == 0) {
#pragma unroll
        for (int e = 0; e < ED; e++) wl[wid][e] = acc[e];
    }
    __syncthreads();
    if (tid < ED) {
        float le = 0.f;
#pragma unroll
        for (int w = 0; w < 8; w++) le += wl[w][tid];
        sm_logits[tid] = le + gate_b[tid];
    }
    __syncthreads();

    if (tid == 0) {
        float l[ED], pr[ED];
        float mx = -1e30f;
#pragma unroll
        for (int e = 0; e < ED; e++) { l[e] = sm_logits[e]; mx = fmaxf(mx, l[e]); }
        float ssum = 0.f;
#pragma unroll
        for (int e = 0; e < ED; e++) { pr[e] = expf(l[e] - mx); ssum += pr[e]; }
        float inv = 1.f / ssum;
#pragma unroll
        for (int e = 0; e < ED; e++) pr[e] *= inv;
        int i0 = 0;
#pragma unroll
        for (int e = 1; e < ED; e++) if (pr[e] > pr[i0]) i0 = e;
        int i1 = (i0 == 0) ? 1 : 0;
#pragma unroll
        for (int e = 0; e < ED; e++) if (e != i0 && pr[e] > pr[i1]) i1 = e;
        float p0 = pr[i0], p1 = pr[i1];
        float dn = 1.f / (p0 + p1 + 1e-9f);
        g_topk_e[t * 2 + 0] = i0;  g_topk_p[t * 2 + 0] = p0 * dn;
        g_topk_e[t * 2 + 1] = i1;  g_topk_p[t * 2 + 1] = p1 * dn;
    }
}

// ---------------- kernel 1: finalize routing + block list + inverse map ----------------
__global__ void __launch_bounds__(1024) finalize_kernel() {
    __shared__ int scnt[ED], soff[ED], sfill[ED];
    int tid = threadIdx.x;
    if (tid < ED) { scnt[tid] = 0; sfill[tid] = 0; }
    __syncthreads();
    for (int j = tid; j < NJOBS; j += 1024) atomicAdd(&scnt[g_topk_e[j]], 1);
    __syncthreads();
    if (tid == 0) {
        int o = 0, nb = 0;
        for (int e = 0; e < ED; e++) {
            soff[e] = o;
            g_off[e] = o;
            g_cnt[e] = scnt[e];
            for (int mm = 0; mm < scnt[e]; mm += 128) {
                g_blk_e[nb] = e;
                g_blk_m[nb] = mm;
                nb++;
            }
            o += scnt[e];
        }
        g_nblk = nb;
    }
    __syncthreads();
    for (int j = tid; j < NJOBS; j += 1024) {
        int e = g_topk_e[j];
        int pos = atomicAdd(&sfill[e], 1);
        int jj = soff[e] + pos;
        g_jobs_tok[jj] = j >> 1;
        g_tok2job[j]   = jj;
    }
}

// ---------------- kernel 2: all converts in one launch (hi planes only) ----------------
#define NX4  ((size_t)TOK * HD / 4)
#define NW4  ((size_t)ED * HD * FD / 4)
__global__ void __launch_bounds__(256) convert_all(const float* __restrict__ x,
                                                   const float* __restrict__ W1,
                                                   const float* __restrict__ W2) {
    size_t i = (size_t)blockIdx.x * 256 + threadIdx.x;
    if (i >= NX4 + 2 * NW4) return;
    const float4* src;
    __half* dst;
    size_t jj;
    if (i < NX4) { src = (const float4*)x; dst = g_xhi; jj = i; }
    else if (i < NX4 + NW4) { src = (const float4*)W1; dst = g_w1hi; jj = i - NX4; }
    else { src = (const float4*)W2; dst = g_w2hi; jj = i - NX4 - NW4; }
    float4 v = src[jj];
    uint32_t hw[2];
    __half h0 = __float2half_rn(v.x), h1 = __float2half_rn(v.y);
    __half h2 = __float2half_rn(v.z), h3 = __float2half_rn(v.w);
    hw[0] = (uint32_t)__half_as_ushort(h0) | ((uint32_t)__half_as_ushort(h1) << 16);
    hw[1] = (uint32_t)__half_as_ushort(h2) | ((uint32_t)__half_as_ushort(h3) << 16);
    ((uint2*)dst)[jj] = make_uint2(hw[0], hw[1]);
}

// ---------------- 1-pass fp16 grouped GEMM, 128m x 256n x 64k, 512 threads ----------------
// (round-12 winner, unchanged: 16 warps 4m x 4n; acc 64 floats/thread; 4 stages x 48KB)
#define STAGES 4
#define STAGE_BYTES 49152
#define SMEM_BYTES (1024 + STAGES * STAGE_BYTES)
#define GTHREADS 512

template <int KDIM, int NDIM, int KSPLIT, bool GATHER, bool DOGELU>
__global__ void __launch_bounds__(GTHREADS, 1)
gemm_mma(const __half* __restrict__ Ahi,  // [rows][KDIM]
         const __half* __restrict__ Whi,  // [E][KDIM][NDIM]
         const float* __restrict__ bias) {
    if ((int)blockIdx.x >= g_nblk) return;
    int e   = g_blk_e[blockIdx.x];
    int m0  = g_blk_m[blockIdx.x];
    int cnt = g_cnt[e];
    int off = g_off[e];
    constexpr int NB = NDIM / 256;
    int ky = blockIdx.y / NB;
    int n0 = (blockIdx.y % NB) * 256;
    constexpr int KSEG = KDIM / KSPLIT;
    int k0g = ky * KSEG;

    extern __shared__ __align__(1024) char smem[];
    uint32_t sb = smem_u32(smem);
    int tid = threadIdx.x, wid = tid >> 5, lane = tid & 31;
    int wm = wid >> 2, wn = wid & 3;   // 4m x 4n warp grid
    int* s_tok = (int*)smem;

    if (GATHER && tid < 128) {
        int r = (m0 + tid < cnt) ? tid : 0;
        s_tok[tid] = g_jobs_tok[off + m0 + r];
    }
    __syncthreads();

    const __half* We_hi = Whi + (size_t)e * KDIM * NDIM + (size_t)k0g * NDIM + n0;
    const float* be = bias + (size_t)e * NDIM;

    // ---- A producer: 2 chunks/thread (r = tid>>3 + q*64; kg = tid&7; 64k per row).
    int akg = tid & 7;
    uint32_t aswz = 16u * (uint32_t)(akg ^ ((tid >> 3) & 7));
    int acol = akg * 8 + k0g;
    const __half* asrc[2];
    uint32_t adst[2];
#pragma unroll
    for (int q = 0; q < 2; q++) {
        int r = (tid >> 3) + q * 64;
        int row;
        if (GATHER) row = s_tok[r];
        else { int rr = (m0 + r < cnt) ? r : 0; row = off + m0 + rr; }
        asrc[q] = Ahi + (size_t)row * KDIM + acol;
        adst[q] = (uint32_t)(r * 128) + aswz;
    }
    // ---- B producer: 4 chunks/thread (kr = tid>>5 + q*16; u = tid&31).
    int bu = tid & 31, bk0 = tid >> 5;
    uint32_t bswz = (uint32_t)((bu >> 3) * 128 + 16 * ((bu & 7) ^ (bk0 & 7)));
    const __half* bsrc_hi = We_hi + (size_t)bk0 * NDIM + bu * 8;

    auto issue = [&](int s, int it) {
        uint32_t base = sb + 1024 + s * STAGE_BYTES;
#pragma unroll
        for (int q = 0; q < 2; q++) cp16(base + adst[q], asrc[q] + it * 64);
        uint32_t bb = base + 16384;
        size_t koff = (size_t)it * 64 * NDIM;
#pragma unroll
        for (int q = 0; q < 4; q++)
            cp16(bb + (uint32_t)((bk0 + q * 16) * 512) + bswz,
                 bsrc_hi + koff + (size_t)(q * 16) * NDIM);
    };

    float acc[16][4];
#pragma unroll
    for (int i = 0; i < 16; i++)
#pragma unroll
        for (int j = 0; j < 4; j++) acc[i][j] = 0.f;

    constexpr int KIT = KSEG / 64;
#pragma unroll
    for (int s = 0; s < STAGES - 1; s++) {
        if (s < KIT) issue(s, s);
        CP_COMMIT();
    }

    int rl = lane & 15, cg = lane >> 4;
    for (int it = 0; it < KIT; it++) {
        CP_WAIT(STAGES - 2);
        __syncthreads();
        uint32_t As = sb + 1024 + (it % STAGES) * STAGE_BYTES;
        uint32_t Bs = As + 16384;
#pragma unroll
        for (int jj = 0; jj < 4; jj++) {
            uint32_t afr[2][4];
#pragma unroll
            for (int mt = 0; mt < 2; mt++) {
                int r = wm * 32 + mt * 16 + rl;
                ldsm_x4(afr[mt], As + r * 128 + 16 * ((jj * 2 + cg) ^ (r & 7)));
            }
            int rB = jj * 16 + rl;
            uint32_t brow = Bs + rB * 512 + wn * 128;
#pragma unroll
            for (int g = 0; g < 4; g++) {
                uint32_t bfr[4];
                ldsm_x4_t(bfr, brow + 16 * ((g * 2 + cg) ^ (rB & 7)));
#pragma unroll
                for (int mt = 0; mt < 2; mt++)
#pragma unroll
                    for (int hh = 0; hh < 2; hh++)
                        mma16816(acc[mt * 8 + g * 2 + hh], afr[mt], &bfr[hh * 2]);
            }
        }
        int nxt = it + STAGES - 1;
        if (nxt < KIT) issue(nxt % STAGES, nxt);
        CP_COMMIT();
    }

    // ---- epilogue ----
#pragma unroll
    for (int mt = 0; mt < 2; mt++) {
#pragma unroll
        for (int nt = 0; nt < 8; nt++) {
            float* d = acc[mt * 8 + nt];
            int nc = n0 + wn * 64 + nt * 8 + 2 * (lane & 3);
            int r0 = m0 + wm * 32 + mt * 16 + (lane >> 2);
            int r1 = r0 + 8;
            if (DOGELU) {
                float b0 = be[nc], b1 = be[nc + 1];
                float c00 = d[0] + b0, c01 = d[1] + b1;
                float c10 = d[2] + b0, c11 = d[3] + b1;
                c00 = 0.5f * c00 * (1.f + erff(c00 * 0.70710678118654752f));
                c01 = 0.5f * c01 * (1.f + erff(c01 * 0.70710678118654752f));
                c10 = 0.5f * c10 * (1.f + erff(c10 * 0.70710678118654752f));
                c11 = 0.5f * c11 * (1.f + erff(c11 * 0.70710678118654752f));
                auto wr = [&](int rr, float a, float b) {
                    size_t base = (size_t)(off + rr) * NDIM + nc;
                    __half h0 = __float2half_rn(a), h1 = __float2half_rn(b);
                    *(uint32_t*)(g_hh + base) =
                        (uint32_t)__half_as_ushort(h0) | ((uint32_t)__half_as_ushort(h1) << 16);
                };
                if (r0 < cnt) wr(r0, c00, c01);
                if (r1 < cnt) wr(r1, c10, c11);
            } else {
                float* ob = g_obuf + (size_t)ky * NJOBS * HD;
                if (r0 < cnt) *(float2*)(ob + (size_t)(off + r0) * NDIM + nc) = make_float2(d[0], d[1]);
                if (r1 < cnt) *(float2*)(ob + (size_t)(off + r1) * NDIM + nc) = make_float2(d[2], d[3]);
            }
        }
    }
}

// ---------------- combine (token-centric): y = sum_k p_k * LN(o0_k + o1_k + b2 + x) ----------------
__global__ void combine_kernel(const float* __restrict__ x,
                               const float* __restrict__ b2,
                               const float* __restrict__ ln_g,
                               const float* __restrict__ ln_b,
                               float* __restrict__ y) {
    int t = blockIdx.x, tid = threadIdx.x;
    int lane = tid & 31, wid = tid >> 5;
    int j0 = g_tok2job[2 * t], j1 = g_tok2job[2 * t + 1];
    int e0 = g_topk_e[2 * t],  e1 = g_topk_e[2 * t + 1];
    float p0 = g_topk_p[2 * t], p1 = g_topk_p[2 * t + 1];

    const float4* xr  = (const float4*)(x + (size_t)t * HD);
    const float4* a0r = (const float4*)(g_obuf + (size_t)j0 * HD);
    const float4* a1r = (const float4*)(g_obuf + (size_t)(NJOBS + j0) * HD);
    const float4* c0r = (const float4*)(g_obuf + (size_t)j1 * HD);
    const float4* c1r = (const float4*)(g_obuf + (size_t)(NJOBS + j1) * HD);
    const float4* b0r = (const float4*)(b2 + (size_t)e0 * HD);
    const float4* b1r = (const float4*)(b2 + (size_t)e1 * HD);

    float4 xv = xr[tid];
    float4 a0 = a0r[tid], a1 = a1r[tid], bb0 = b0r[tid];
    float4 c0 = c0r[tid], c1 = c1r[tid], bb1 = b1r[tid];
    float v0[4] = {a0.x + a1.x + bb0.x + xv.x, a0.y + a1.y + bb0.y + xv.y,
                   a0.z + a1.z + bb0.z + xv.z, a0.w + a1.w + bb0.w + xv.w};
    float v1[4] = {c0.x + c1.x + bb1.x + xv.x, c0.y + c1.y + bb1.y + xv.y,
                   c0.z + c1.z + bb1.z + xv.z, c0.w + c1.w + bb1.w + xv.w};

    float s0 = 0.f, q0 = 0.f, s1 = 0.f, q1 = 0.f;
#pragma unroll
    for (int i = 0; i < 4; i++) {
        s0 += v0[i]; q0 += v0[i] * v0[i];
        s1 += v1[i]; q1 += v1[i] * v1[i];
    }
#pragma unroll
    for (int o = 16; o > 0; o >>= 1) {
        s0 += __shfl_xor_sync(0xFFFFFFFFu, s0, o);
        q0 += __shfl_xor_sync(0xFFFFFFFFu, q0, o);
        s1 += __shfl_xor_sync(0xFFFFFFFFu, s1, o);
        q1 += __shfl_xor_sync(0xFFFFFFFFu, q1, o);
    }
    __shared__ float ws[4][8];
    __shared__ float st0, st1, sr0, sr1;
    if (lane == 0) { ws[0][wid] = s0; ws[1][wid] = q0; ws[2][wid] = s1; ws[3][wid] = q1; }
    __syncthreads();
    if (tid == 0) {
        float ts0 = 0.f, tq0 = 0.f, ts1 = 0.f, tq1 = 0.f;
#pragma unroll
        for (int w = 0; w < 8; w++) {
            ts0 += ws[0][w]; tq0 += ws[1][w]; ts1 += ws[2][w]; tq1 += ws[3][w];
        }
        float m0 = ts0 * (1.f / HD), m1 = ts1 * (1.f / HD);
        st0 = m0; st1 = m1;
        sr0 = rsqrtf(tq0 * (1.f / HD) - m0 * m0 + 1e-5f);
        sr1 = rsqrtf(tq1 * (1.f / HD) - m1 * m1 + 1e-5f);
    }
    __syncthreads();
    float m0 = st0, r0 = sr0, m1 = st1, r1 = sr1;

    float out[4];
#pragma unroll
    for (int i = 0; i < 4; i++) {
        int h = tid * 4 + i;
        float o0 = (v0[i] - m0) * r0 * ln_g[(size_t)e0 * HD + h] + ln_b[(size_t)e0 * HD + h];
        float o1 = (v1[i] - m1) * r1 * ln_g[(size_t)e1 * HD + h] + ln_b[(size_t)e1 * HD + h];
        out[i] = o0 * p0 + o1 * p1;
    }
    *(float4*)(y + (size_t)t * HD + tid * 4) = *(float4*)out;
}

// ---------------- launch ----------------
extern "C" void kernel_launch(void* const* d_in, const int* in_sizes, int n_in,
                              void* d_out, int out_size) {
    const float* x      = (const float*)d_in[0];
    const float* W1     = (const float*)d_in[1];
    const float* b1     = (const float*)d_in[2];
    const float* W2     = (const float*)d_in[3];
    const float* b2     = (const float*)d_in[4];
    const float* ln_g   = (const float*)d_in[5];
    const float* ln_b   = (const float*)d_in[6];
    const float* gn_g   = (const float*)d_in[7];
    const float* gn_b   = (const float*)d_in[8];
    const float* gate_w = (const float*)d_in[9];
    const float* gate_b = (const float*)d_in[10];
    float* y = (float*)d_out;

    __half *xhi, *w1hi, *w2hi, *hh;
    cudaGetSymbolAddress((void**)&xhi,  g_xhi);
    cudaGetSymbolAddress((void**)&w1hi, g_w1hi);
    cudaGetSymbolAddress((void**)&w2hi, g_w2hi);
    cudaGetSymbolAddress((void**)&hh,   g_hh);

    cudaFuncSetAttribute(gemm_mma<HD, FD, 1, true, true>,
                         cudaFuncAttributeMaxDynamicSharedMemorySize, SMEM_BYTES);
    cudaFuncSetAttribute(gemm_mma<FD, HD, 2, false, false>,
                         cudaFuncAttributeMaxDynamicSharedMemorySize, SMEM_BYTES);

    // 0: gating; 1: routing finalize; 2: converts; 3: GEMM1 (ncu slot)
    gate_kernel<<<TOK, 256>>>(x, gn_g, gn_b, gate_w, gate_b);
    finalize_kernel<<<1, 1024>>>();
    {
        size_t total = NX4 + 2 * NW4;
        convert_all<<<(unsigned)((total + 255) / 256), 256>>>(x, W1, W2);
    }
    // GEMM1: h = gelu(x @ W1[e] + b1[e]); K=1024 (16 k-iters), N=4096
    gemm_mma<HD, FD, 1, true, true>
        <<<dim3(MAXBLK, FD / 256), GTHREADS, SMEM_BYTES>>>(xhi, w1hi, b1);
    // GEMM2: partials = h @ W2[e]; K=4096 split x2 (32 k-iters each), N=1024
    gemm_mma<FD, HD, 2, false, false>
        <<<dim3(MAXBLK, (HD / 256) * 2), GTHREADS, SMEM_BYTES>>>(hh, w2hi, b2);

    // token-centric combine: plain stores, no memset, no atomics
    combine_kernel<<<TOK, 256>>>(x, b2, ln_g, ln_b, y);
}

// round 16
// speedup vs baseline: 1.1103x; 1.0151x over previous
#include <cuda_runtime.h>
#include <cuda_fp16.h>
#include <math.h>
#include <stdint.h>

#define TOK   8192
#define HD    1024
#define FD    4096
#define ED    8
#define NJOBS (TOK * 2)
#define MAXBLK 136

// ---------------- device scratch ----------------
__device__ __half g_xhi[(size_t)TOK * HD];
__device__ __half g_w1hi[(size_t)ED * HD * FD];
__device__ __half g_w2hi[(size_t)ED * FD * HD];
__device__ __half g_hh[(size_t)NJOBS * FD];
__device__ float  g_obuf[(size_t)2 * NJOBS * HD];   // two K-split partials for GEMM2
__device__ int    g_jobs_tok[NJOBS];
__device__ int    g_tok2job[NJOBS];
__device__ int    g_cnt[ED];
__device__ int    g_off[ED];
__device__ int    g_topk_e[NJOBS];
__device__ float  g_topk_p[NJOBS];
__device__ int    g_blk_e[MAXBLK];
__device__ int    g_blk_m[MAXBLK];
__device__ int    g_nblk;

// ---------------- PTX helpers (sm_80-class only) ----------------
__device__ __forceinline__ uint32_t smem_u32(const void* p) {
    uint32_t a;
    asm("{ .reg .u64 t; cvta.to.shared.u64 t, %1; cvt.u32.u64 %0, t; }" : "=r"(a) : "l"(p));
    return a;
}
__device__ __forceinline__ void ldsm_x4(uint32_t* r, uint32_t addr) {
    asm volatile("ldmatrix.sync.aligned.m8n8.x4.shared.b16 {%0,%1,%2,%3}, [%4];"
        : "=r"(r[0]), "=r"(r[1]), "=r"(r[2]), "=r"(r[3]) : "r"(addr));
}
__device__ __forceinline__ void ldsm_x4_t(uint32_t* r, uint32_t addr) {
    asm volatile("ldmatrix.sync.aligned.m8n8.x4.trans.shared.b16 {%0,%1,%2,%3}, [%4];"
        : "=r"(r[0]), "=r"(r[1]), "=r"(r[2]), "=r"(r[3]) : "r"(addr));
}
__device__ __forceinline__ void mma16816(float* d, const uint32_t* a, const uint32_t* b) {
    asm volatile("mma.sync.aligned.m16n8k16.row.col.f32.f16.f16.f32 "
        "{%0,%1,%2,%3}, {%4,%5,%6,%7}, {%8,%9}, {%0,%1,%2,%3};"
        : "+f"(d[0]), "+f"(d[1]), "+f"(d[2]), "+f"(d[3])
        : "r"(a[0]), "r"(a[1]), "r"(a[2]), "r"(a[3]), "r"(b[0]), "r"(b[1]));
}
__device__ __forceinline__ void cp16(uint32_t dst, const void* src) {
    asm volatile("cp.async.cg.shared.global [%0], [%1], 16;"
        :: "r"(dst), "l"(__cvta_generic_to_global(src)) : "memory");
}
#define CP_COMMIT() asm volatile("cp.async.commit_group;" ::: "memory")
#define CP_WAIT(n)  asm volatile("cp.async.wait_group %0;" :: "n"(n) : "memory")

// ---------------- kernel 0: gating (shuffle reductions, 4 barriers) ----------------
__global__ void gate_kernel(const float* __restrict__ x,
                            const float* __restrict__ gn_g,
                            const float* __restrict__ gn_b,
                            const float* __restrict__ gate_w,
                            const float* __restrict__ gate_b) {
    int t = blockIdx.x, tid = threadIdx.x;
    int lane = tid & 31, wid = tid >> 5;   // 8 warps
    const float4* xr4 = (const float4*)(x + (size_t)t * HD);

    __shared__ float ws[8], ws2[8];
    __shared__ float wl[8][8];
    __shared__ float sm_mean, sm_rstd;
    __shared__ float sm_logits[ED];

    float4 xv = xr4[tid];
    float xs[4] = {xv.x, xv.y, xv.z, xv.w};
    float s = 0.f, s2 = 0.f;
#pragma unroll
    for (int i = 0; i < 4; i++) { s += xs[i]; s2 += xs[i] * xs[i]; }
#pragma unroll
    for (int o = 16; o > 0; o >>= 1) {
        s  += __shfl_xor_sync(0xFFFFFFFFu, s,  o);
        s2 += __shfl_xor_sync(0xFFFFFFFFu, s2, o);
    }
    if (lane == 0) { ws[wid] = s; ws2[wid] = s2; }
    __syncthreads();
    if (tid == 0) {
        float ts = 0.f, ts2 = 0.f;
#pragma unroll
        for (int w = 0; w < 8; w++) { ts += ws[w]; ts2 += ws2[w]; }
        float m = ts * (1.f / HD);
        sm_mean = m;
        sm_rstd = rsqrtf(ts2 * (1.f / HD) - m * m + 1e-5f);
    }
    __syncthreads();

    float m = sm_mean, r = sm_rstd;
    float acc[ED];
#pragma unroll
    for (int e = 0; e < ED; e++) acc[e] = 0.f;
#pragma unroll
    for (int i = 0; i < 4; i++) {
        int h = tid * 4 + i;
        float xn = (xs[i] - m) * r * gn_g[h] + gn_b[h];
#pragma unroll
        for (int e = 0; e < ED; e++) acc[e] += xn * gate_w[h * ED + e];
    }
#pragma unroll
    for (int e = 0; e < ED; e++)
#pragma unroll
        for (int o = 16; o > 0; o >>= 1)
            acc[e] += __shfl_xor_sync(0xFFFFFFFFu, acc[e], o);
    if (lane == 0) {
#pragma unroll
        for (int e = 0; e < ED; e++) wl[wid][e] = acc[e];
    }
    __syncthreads();
    if (tid < ED) {
        float le = 0.f;
#pragma unroll
        for (int w = 0; w < 8; w++) le += wl[w][tid];
        sm_logits[tid] = le + gate_b[tid];
    }
    __syncthreads();

    if (tid == 0) {
        float l[ED], pr[ED];
        float mx = -1e30f;
#pragma unroll
        for (int e = 0; e < ED; e++) { l[e] = sm_logits[e]; mx = fmaxf(mx, l[e]); }
        float ssum = 0.f;
#pragma unroll
        for (int e = 0; e < ED; e++) { pr[e] = expf(l[e] - mx); ssum += pr[e]; }
        float inv = 1.f / ssum;
#pragma unroll
        for (int e = 0; e < ED; e++) pr[e] *= inv;
        int i0 = 0;
#pragma unroll
        for (int e = 1; e < ED; e++) if (pr[e] > pr[i0]) i0 = e;
        int i1 = (i0 == 0) ? 1 : 0;
#pragma unroll
        for (int e = 0; e < ED; e++) if (e != i0 && pr[e] > pr[i1]) i1 = e;
        float p0 = pr[i0], p1 = pr[i1];
        float dn = 1.f / (p0 + p1 + 1e-9f);
        g_topk_e[t * 2 + 0] = i0;  g_topk_p[t * 2 + 0] = p0 * dn;
        g_topk_e[t * 2 + 1] = i1;  g_topk_p[t * 2 + 1] = p1 * dn;
    }
}

// ---------------- kernel 1: finalize routing + block list + inverse map ----------------
__global__ void __launch_bounds__(1024) finalize_kernel() {
    __shared__ int scnt[ED], soff[ED], sfill[ED];
    int tid = threadIdx.x;
    if (tid < ED) { scnt[tid] = 0; sfill[tid] = 0; }
    __syncthreads();
    for (int j = tid; j < NJOBS; j += 1024) atomicAdd(&scnt[g_topk_e[j]], 1);
    __syncthreads();
    if (tid == 0) {
        int o = 0, nb = 0;
        for (int e = 0; e < ED; e++) {
            soff[e] = o;
            g_off[e] = o;
            g_cnt[e] = scnt[e];
            for (int mm = 0; mm < scnt[e]; mm += 128) {
                g_blk_e[nb] = e;
                g_blk_m[nb] = mm;
                nb++;
            }
            o += scnt[e];
        }
        g_nblk = nb;
    }
    __syncthreads();
    for (int j = tid; j < NJOBS; j += 1024) {
        int e = g_topk_e[j];
        int pos = atomicAdd(&sfill[e], 1);
        int jj = soff[e] + pos;
        g_jobs_tok[jj] = j >> 1;
        g_tok2job[j]   = jj;
    }
}

// ---------------- converts (hi planes only), split for overlap ----------------
#define NX4  ((size_t)TOK * HD / 4)
#define NW4  ((size_t)ED * HD * FD / 4)
__device__ __forceinline__ void cvt4(const float4* src, __half* dst, size_t jj) {
    float4 v = src[jj];
    uint32_t hw[2];
    __half h0 = __float2half_rn(v.x), h1 = __float2half_rn(v.y);
    __half h2 = __float2half_rn(v.z), h3 = __float2half_rn(v.w);
    hw[0] = (uint32_t)__half_as_ushort(h0) | ((uint32_t)__half_as_ushort(h1) << 16);
    hw[1] = (uint32_t)__half_as_ushort(h2) | ((uint32_t)__half_as_ushort(h3) << 16);
    ((uint2*)dst)[jj] = make_uint2(hw[0], hw[1]);
}
__global__ void __launch_bounds__(256) convert_xw1(const float* __restrict__ x,
                                                   const float* __restrict__ W1) {
    size_t i = (size_t)blockIdx.x * 256 + threadIdx.x;
    if (i < NX4) cvt4((const float4*)x, g_xhi, i);
    else if (i < NX4 + NW4) cvt4((const float4*)W1, g_w1hi, i - NX4);
}
__global__ void __launch_bounds__(256) convert_w2(const float* __restrict__ W2) {
    size_t i = (size_t)blockIdx.x * 256 + threadIdx.x;
    if (i < NW4) cvt4((const float4*)W2, g_w2hi, i);
}

// ---------------- 1-pass fp16 grouped GEMM, 128m x 256n x 64k, 512 threads ----------------
// (round-12 winner, unchanged: 16 warps 4m x 4n; acc 64 floats/thread; 4 stages x 48KB)
#define STAGES 4
#define STAGE_BYTES 49152
#define SMEM_BYTES (1024 + STAGES * STAGE_BYTES)
#define GTHREADS 512

template <int KDIM, int NDIM, int KSPLIT, bool GATHER, bool DOGELU>
__global__ void __launch_bounds__(GTHREADS, 1)
gemm_mma(const __half* __restrict__ Ahi,  // [rows][KDIM]
         const __half* __restrict__ Whi,  // [E][KDIM][NDIM]
         const float* __restrict__ bias) {
    if ((int)blockIdx.x >= g_nblk) return;
    int e   = g_blk_e[blockIdx.x];
    int m0  = g_blk_m[blockIdx.x];
    int cnt = g_cnt[e];
    int off = g_off[e];
    constexpr int NB = NDIM / 256;
    int ky = blockIdx.y / NB;
    int n0 = (blockIdx.y % NB) * 256;
    constexpr int KSEG = KDIM / KSPLIT;
    int k0g = ky * KSEG;

    extern __shared__ __align__(1024) char smem[];
    uint32_t sb = smem_u32(smem);
    int tid = threadIdx.x, wid = tid >> 5, lane = tid & 31;
    int wm = wid >> 2, wn = wid & 3;   // 4m x 4n warp grid
    int* s_tok = (int*)smem;

    if (GATHER && tid < 128) {
        int r = (m0 + tid < cnt) ? tid : 0;
        s_tok[tid] = g_jobs_tok[off + m0 + r];
    }
    __syncthreads();

    const __half* We_hi = Whi + (size_t)e * KDIM * NDIM + (size_t)k0g * NDIM + n0;
    const float* be = bias + (size_t)e * NDIM;

    // ---- A producer: 2 chunks/thread (r = tid>>3 + q*64; kg = tid&7; 64k per row).
    int akg = tid & 7;
    uint32_t aswz = 16u * (uint32_t)(akg ^ ((tid >> 3) & 7));
    int acol = akg * 8 + k0g;
    const __half* asrc[2];
    uint32_t adst[2];
#pragma unroll
    for (int q = 0; q < 2; q++) {
        int r = (tid >> 3) + q * 64;
        int row;
        if (GATHER) row = s_tok[r];
        else { int rr = (m0 + r < cnt) ? r : 0; row = off + m0 + rr; }
        asrc[q] = Ahi + (size_t)row * KDIM + acol;
        adst[q] = (uint32_t)(r * 128) + aswz;
    }
    // ---- B producer: 4 chunks/thread (kr = tid>>5 + q*16; u = tid&31).
    int bu = tid & 31, bk0 = tid >> 5;
    uint32_t bswz = (uint32_t)((bu >> 3) * 128 + 16 * ((bu & 7) ^ (bk0 & 7)));
    const __half* bsrc_hi = We_hi + (size_t)bk0 * NDIM + bu * 8;

    auto issue = [&](int s, int it) {
        uint32_t base = sb + 1024 + s * STAGE_BYTES;
#pragma unroll
        for (int q = 0; q < 2; q++) cp16(base + adst[q], asrc[q] + it * 64);
        uint32_t bb = base + 16384;
        size_t koff = (size_t)it * 64 * NDIM;
#pragma unroll
        for (int q = 0; q < 4; q++)
            cp16(bb + (uint32_t)((bk0 + q * 16) * 512) + bswz,
                 bsrc_hi + koff + (size_t)(q * 16) * NDIM);
    };

    float acc[16][4];
#pragma unroll
    for (int i = 0; i < 16; i++)
#pragma unroll
        for (int j = 0; j < 4; j++) acc[i][j] = 0.f;

    constexpr int KIT = KSEG / 64;
#pragma unroll
    for (int s = 0; s < STAGES - 1; s++) {
        if (s < KIT) issue(s, s);
        CP_COMMIT();
    }

    int rl = lane & 15, cg = lane >> 4;
    for (int it = 0; it < KIT; it++) {
        CP_WAIT(STAGES - 2);
        __syncthreads();
        uint32_t As = sb + 1024 + (it % STAGES) * STAGE_BYTES;
        uint32_t Bs = As + 16384;
#pragma unroll
        for (int jj = 0; jj < 4; jj++) {
            uint32_t afr[2][4];
#pragma unroll
            for (int mt = 0; mt < 2; mt++) {
                int r = wm * 32 + mt * 16 + rl;
                ldsm_x4(afr[mt], As + r * 128 + 16 * ((jj * 2 + cg) ^ (r & 7)));
            }
            int rB = jj * 16 + rl;
            uint32_t brow = Bs + rB * 512 + wn * 128;
#pragma unroll
            for (int g = 0; g < 4; g++) {
                uint32_t bfr[4];
                ldsm_x4_t(bfr, brow + 16 * ((g * 2 + cg) ^ (rB & 7)));
#pragma unroll
                for (int mt = 0; mt < 2; mt++)
#pragma unroll
                    for (int hh = 0; hh < 2; hh++)
                        mma16816(acc[mt * 8 + g * 2 + hh], afr[mt], &bfr[hh * 2]);
            }
        }
        int nxt = it + STAGES - 1;
        if (nxt < KIT) issue(nxt % STAGES, nxt);
        CP_COMMIT();
    }

    // ---- epilogue ----
#pragma unroll
    for (int mt = 0; mt < 2; mt++) {
#pragma unroll
        for (int nt = 0; nt < 8; nt++) {
            float* d = acc[mt * 8 + nt];
            int nc = n0 + wn * 64 + nt * 8 + 2 * (lane & 3);
            int r0 = m0 + wm * 32 + mt * 16 + (lane >> 2);
            int r1 = r0 + 8;
            if (DOGELU) {
                float b0 = be[nc], b1 = be[nc + 1];
                float c00 = d[0] + b0, c01 = d[1] + b1;
                float c10 = d[2] + b0, c11 = d[3] + b1;
                c00 = 0.5f * c00 * (1.f + erff(c00 * 0.70710678118654752f));
                c01 = 0.5f * c01 * (1.f + erff(c01 * 0.70710678118654752f));
                c10 = 0.5f * c10 * (1.f + erff(c10 * 0.70710678118654752f));
                c11 = 0.5f * c11 * (1.f + erff(c11 * 0.70710678118654752f));
                auto wr = [&](int rr, float a, float b) {
                    size_t base = (size_t)(off + rr) * NDIM + nc;
                    __half h0 = __float2half_rn(a), h1 = __float2half_rn(b);
                    *(uint32_t*)(g_hh + base) =
                        (uint32_t)__half_as_ushort(h0) | ((uint32_t)__half_as_ushort(h1) << 16);
                };
                if (r0 < cnt) wr(r0, c00, c01);
                if (r1 < cnt) wr(r1, c10, c11);
            } else {
                float* ob = g_obuf + (size_t)ky * NJOBS * HD;
                if (r0 < cnt) *(float2*)(ob + (size_t)(off + r0) * NDIM + nc) = make_float2(d[0], d[1]);
                if (r1 < cnt) *(float2*)(ob + (size_t)(off + r1) * NDIM + nc) = make_float2(d[2], d[3]);
            }
        }
    }
}

// ---------------- combine (token-centric): y = sum_k p_k * LN(o0_k + o1_k + b2 + x) ----------------
__global__ void combine_kernel(const float* __restrict__ x,
                               const float* __restrict__ b2,
                               const float* __restrict__ ln_g,
                               const float* __restrict__ ln_b,
                               float* __restrict__ y) {
    int t = blockIdx.x, tid = threadIdx.x;
    int lane = tid & 31, wid = tid >> 5;
    int j0 = g_tok2job[2 * t], j1 = g_tok2job[2 * t + 1];
    int e0 = g_topk_e[2 * t],  e1 = g_topk_e[2 * t + 1];
    float p0 = g_topk_p[2 * t], p1 = g_topk_p[2 * t + 1];

    const float4* xr  = (const float4*)(x + (size_t)t * HD);
    const float4* a0r = (const float4*)(g_obuf + (size_t)j0 * HD);
    const float4* a1r = (const float4*)(g_obuf + (size_t)(NJOBS + j0) * HD);
    const float4* c0r = (const float4*)(g_obuf + (size_t)j1 * HD);
    const float4* c1r = (const float4*)(g_obuf + (size_t)(NJOBS + j1) * HD);
    const float4* b0r = (const float4*)(b2 + (size_t)e0 * HD);
    const float4* b1r = (const float4*)(b2 + (size_t)e1 * HD);

    float4 xv = xr[tid];
    float4 a0 = a0r[tid], a1 = a1r[tid], bb0 = b0r[tid];
    float4 c0 = c0r[tid], c1 = c1r[tid], bb1 = b1r[tid];
    float v0[4] = {a0.x + a1.x + bb0.x + xv.x, a0.y + a1.y + bb0.y + xv.y,
                   a0.z + a1.z + bb0.z + xv.z, a0.w + a1.w + bb0.w + xv.w};
    float v1[4] = {c0.x + c1.x + bb1.x + xv.x, c0.y + c1.y + bb1.y + xv.y,
                   c0.z + c1.z + bb1.z + xv.z, c0.w + c1.w + bb1.w + xv.w};

    float s0 = 0.f, q0 = 0.f, s1 = 0.f, q1 = 0.f;
#pragma unroll
    for (int i = 0; i < 4; i++) {
        s0 += v0[i]; q0 += v0[i] * v0[i];
        s1 += v1[i]; q1 += v1[i] * v1[i];
    }
#pragma unroll
    for (int o = 16; o > 0; o >>= 1) {
        s0 += __shfl_xor_sync(0xFFFFFFFFu, s0, o);
        q0 += __shfl_xor_sync(0xFFFFFFFFu, q0, o);
        s1 += __shfl_xor_sync(0xFFFFFFFFu, s1, o);
        q1 += __shfl_xor_sync(0xFFFFFFFFu, q1, o);
    }
    __shared__ float ws[4][8];
    __shared__ float st0, st1, sr0, sr1;
    if (lane == 0) { ws[0][wid] = s0; ws[1][wid] = q0; ws[2][wid] = s1; ws[3][wid] = q1; }
    __syncthreads();
    if (tid == 0) {
        float ts0 = 0.f, tq0 = 0.f, ts1 = 0.f, tq1 = 0.f;
#pragma unroll
        for (int w = 0; w < 8; w++) {
            ts0 += ws[0][w]; tq0 += ws[1][w]; ts1 += ws[2][w]; tq1 += ws[3][w];
        }
        float m0 = ts0 * (1.f / HD), m1 = ts1 * (1.f / HD);
        st0 = m0; st1 = m1;
        sr0 = rsqrtf(tq0 * (1.f / HD) - m0 * m0 + 1e-5f);
        sr1 = rsqrtf(tq1 * (1.f / HD) - m1 * m1 + 1e-5f);
    }
    __syncthreads();
    float m0 = st0, r0 = sr0, m1 = st1, r1 = sr1;

    float out[4];
#pragma unroll
    for (int i = 0; i < 4; i++) {
        int h = tid * 4 + i;
        float o0 = (v0[i] - m0) * r0 * ln_g[(size_t)e0 * HD + h] + ln_b[(size_t)e0 * HD + h];
        float o1 = (v1[i] - m1) * r1 * ln_g[(size_t)e1 * HD + h] + ln_b[(size_t)e1 * HD + h];
        out[i] = o0 * p0 + o1 * p1;
    }
    *(float4*)(y + (size_t)t * HD + tid * 4) = *(float4*)out;
}

// ---------------- launch (multi-stream fork/join, graph-capturable) ----------------
extern "C" void kernel_launch(void* const* d_in, const int* in_sizes, int n_in,
                              void* d_out, int out_size) {
    const float* x      = (const float*)d_in[0];
    const float* W1     = (const float*)d_in[1];
    const float* b1     = (const float*)d_in[2];
    const float* W2     = (const float*)d_in[3];
    const float* b2     = (const float*)d_in[4];
    const float* ln_g   = (const float*)d_in[5];
    const float* ln_b   = (const float*)d_in[6];
    const float* gn_g   = (const float*)d_in[7];
    const float* gn_b   = (const float*)d_in[8];
    const float* gate_w = (const float*)d_in[9];
    const float* gate_b = (const float*)d_in[10];
    float* y = (float*)d_out;

    __half *xhi, *w1hi, *w2hi, *hh;
    cudaGetSymbolAddress((void**)&xhi,  g_xhi);
    cudaGetSymbolAddress((void**)&w1hi, g_w1hi);
    cudaGetSymbolAddress((void**)&w2hi, g_w2hi);
    cudaGetSymbolAddress((void**)&hh,   g_hh);

    cudaFuncSetAttribute(gemm_mma<HD, FD, 1, true, true>,
                         cudaFuncAttributeMaxDynamicSharedMemorySize, SMEM_BYTES);
    cudaFuncSetAttribute(gemm_mma<FD, HD, 2, false, false>,
                         cudaFuncAttributeMaxDynamicSharedMemorySize, SMEM_BYTES);

    // side stream + events (host objects only; no device memory)
    cudaStream_t s1;
    cudaStreamCreateWithFlags(&s1, cudaStreamNonBlocking);
    cudaEvent_t ev0, ev1, ev2;
    cudaEventCreateWithFlags(&ev0, cudaEventDisableTiming);
    cudaEventCreateWithFlags(&ev1, cudaEventDisableTiming);
    cudaEventCreateWithFlags(&ev2, cudaEventDisableTiming);

    // fork: side stream joins the capture graph at the origin
    cudaEventRecord(ev0, 0);
    cudaStreamWaitEvent(s1, ev0, 0);

    // main stream: routing (launch idx 0, 1)
    gate_kernel<<<TOK, 256>>>(x, gn_g, gn_b, gate_w, gate_b);
    finalize_kernel<<<1, 1024>>>();

    // side stream: convert x + W1 (idx 2), concurrent with gate/finalize
    {
        size_t total = NX4 + NW4;
        convert_xw1<<<(unsigned)((total + 255) / 256), 256, 0, s1>>>(x, W1);
    }
    cudaEventRecord(ev1, s1);
    cudaStreamWaitEvent(0, ev1, 0);

    // GEMM1 (idx 3 — ncu slot): h = gelu(x @ W1[e] + b1[e]); K=1024, N=4096
    gemm_mma<HD, FD, 1, true, true>
        <<<dim3(MAXBLK, FD / 256), GTHREADS, SMEM_BYTES>>>(xhi, w1hi, b1);

    // side stream: convert W2 (idx 4), concurrent with GEMM1
    convert_w2<<<(unsigned)((NW4 + 255) / 256), 256, 0, s1>>>(W2);
    cudaEventRecord(ev2, s1);
    cudaStreamWaitEvent(0, ev2, 0);

    // GEMM2 (idx 5): partials = h @ W2[e]; K=4096 split x2, N=1024
    gemm_mma<FD, HD, 2, false, false>
        <<<dim3(MAXBLK, (HD / 256) * 2), GTHREADS, SMEM_BYTES>>>(hh, w2hi, b2);

    // combine (idx 6): token-centric, plain stores
    combine_kernel<<<TOK, 256>>>(x, b2, ln_g, ln_b, y);
}

// round 17
// speedup vs baseline: 1.1373x; 1.0243x over previous
#include <cuda_runtime.h>
#include <cuda_fp16.h>
#include <math.h>
#include <stdint.h>

#define TOK   8192
#define HD    1024
#define FD    4096
#define ED    8
#define NJOBS (TOK * 2)
#define MAXBLK 136

// ---------------- device scratch ----------------
__device__ __half g_xhi[(size_t)TOK * HD];
__device__ __half g_w1hi[(size_t)ED * HD * FD];
__device__ __half g_w2hi[(size_t)ED * FD * HD];
__device__ __half g_hh[(size_t)NJOBS * FD];
__device__ float  g_obuf[(size_t)NJOBS * HD];
__device__ int    g_jobs_tok[NJOBS];
__device__ int    g_tok2job[NJOBS];
__device__ int    g_cnt[ED];
__device__ int    g_off[ED];
__device__ int    g_topk_e[NJOBS];
__device__ float  g_topk_p[NJOBS];
__device__ int    g_blk_e[MAXBLK];
__device__ int    g_blk_m[MAXBLK];
__device__ int    g_nblk;

// ---------------- PTX helpers (sm_80-class only) ----------------
__device__ __forceinline__ uint32_t smem_u32(const void* p) {
    uint32_t a;
    asm("{ .reg .u64 t; cvta.to.shared.u64 t, %1; cvt.u32.u64 %0, t; }" : "=r"(a) : "l"(p));
    return a;
}
__device__ __forceinline__ void ldsm_x4(uint32_t* r, uint32_t addr) {
    asm volatile("ldmatrix.sync.aligned.m8n8.x4.shared.b16 {%0,%1,%2,%3}, [%4];"
        : "=r"(r[0]), "=r"(r[1]), "=r"(r[2]), "=r"(r[3]) : "r"(addr));
}
__device__ __forceinline__ void ldsm_x4_t(uint32_t* r, uint32_t addr) {
    asm volatile("ldmatrix.sync.aligned.m8n8.x4.trans.shared.b16 {%0,%1,%2,%3}, [%4];"
        : "=r"(r[0]), "=r"(r[1]), "=r"(r[2]), "=r"(r[3]) : "r"(addr));
}
__device__ __forceinline__ void mma16816(float* d, const uint32_t* a, const uint32_t* b) {
    asm volatile("mma.sync.aligned.m16n8k16.row.col.f32.f16.f16.f32 "
        "{%0,%1,%2,%3}, {%4,%5,%6,%7}, {%8,%9}, {%0,%1,%2,%3};"
        : "+f"(d[0]), "+f"(d[1]), "+f"(d[2]), "+f"(d[3])
        : "r"(a[0]), "r"(a[1]), "r"(a[2]), "r"(a[3]), "r"(b[0]), "r"(b[1]));
}
__device__ __forceinline__ void cp16(uint32_t dst, const void* src) {
    asm volatile("cp.async.cg.shared.global [%0], [%1], 16;"
        :: "r"(dst), "l"(__cvta_generic_to_global(src)) : "memory");
}
#define CP_COMMIT() asm volatile("cp.async.commit_group;" ::: "memory")
#define CP_WAIT(n)  asm volatile("cp.async.wait_group %0;" :: "n"(n) : "memory")

// ---------------- kernel 0: gating (shuffle reductions, 4 barriers) ----------------
__global__ void gate_kernel(const float* __restrict__ x,
                            const float* __restrict__ gn_g,
                            const float* __restrict__ gn_b,
                            const float* __restrict__ gate_w,
                            const float* __restrict__ gate_b) {
    int t = blockIdx.x, tid = threadIdx.x;
    int lane = tid & 31, wid = tid >> 5;   // 8 warps
    const float4* xr4 = (const float4*)(x + (size_t)t * HD);

    __shared__ float ws[8], ws2[8];
    __shared__ float wl[8][8];
    __shared__ float sm_mean, sm_rstd;
    __shared__ float sm_logits[ED];

    float4 xv = xr4[tid];
    float xs[4] = {xv.x, xv.y, xv.z, xv.w};
    float s = 0.f, s2 = 0.f;
#pragma unroll
    for (int i = 0; i < 4; i++) { s += xs[i]; s2 += xs[i] * xs[i]; }
#pragma unroll
    for (int o = 16; o > 0; o >>= 1) {
        s  += __shfl_xor_sync(0xFFFFFFFFu, s,  o);
        s2 += __shfl_xor_sync(0xFFFFFFFFu, s2, o);
    }
    if (lane == 0) { ws[wid] = s; ws2[wid] = s2; }
    __syncthreads();
    if (tid == 0) {
        float ts = 0.f, ts2 = 0.f;
#pragma unroll
        for (int w = 0; w < 8; w++) { ts += ws[w]; ts2 += ws2[w]; }
        float m = ts * (1.f / HD);
        sm_mean = m;
        sm_rstd = rsqrtf(ts2 * (1.f / HD) - m * m + 1e-5f);
    }
    __syncthreads();

    float m = sm_mean, r = sm_rstd;
    float acc[ED];
#pragma unroll
    for (int e = 0; e < ED; e++) acc[e] = 0.f;
#pragma unroll
    for (int i = 0; i < 4; i++) {
        int h = tid * 4 + i;
        float xn = (xs[i] - m) * r * gn_g[h] + gn_b[h];
#pragma unroll
        for (int e = 0; e < ED; e++) acc[e] += xn * gate_w[h * ED + e];
    }
#pragma unroll
    for (int e = 0; e < ED; e++)
#pragma unroll
        for (int o = 16; o > 0; o >>= 1)
            acc[e] += __shfl_xor_sync(0xFFFFFFFFu, acc[e], o);
    if (lane == 0) {
#pragma unroll
        for (int e = 0; e < ED; e++) wl[wid][e] = acc[e];
    }
    __syncthreads();
    if (tid < ED) {
        float le = 0.f;
#pragma unroll
        for (int w = 0; w < 8; w++) le += wl[w][tid];
        sm_logits[tid] = le + gate_b[tid];
    }
    __syncthreads();

    if (tid == 0) {
        float l[ED], pr[ED];
        float mx = -1e30f;
#pragma unroll
        for (int e = 0; e < ED; e++) { l[e] = sm_logits[e]; mx = fmaxf(mx, l[e]); }
        float ssum = 0.f;
#pragma unroll
        for (int e = 0; e < ED; e++) { pr[e] = expf(l[e] - mx); ssum += pr[e]; }
        float inv = 1.f / ssum;
#pragma unroll
        for (int e = 0; e < ED; e++) pr[e] *= inv;
        int i0 = 0;
#pragma unroll
        for (int e = 1; e < ED; e++) if (pr[e] > pr[i0]) i0 = e;
        int i1 = (i0 == 0) ? 1 : 0;
#pragma unroll
        for (int e = 0; e < ED; e++) if (e != i0 && pr[e] > pr[i1]) i1 = e;
        float p0 = pr[i0], p1 = pr[i1];
        float dn = 1.f / (p0 + p1 + 1e-9f);
        g_topk_e[t * 2 + 0] = i0;  g_topk_p[t * 2 + 0] = p0 * dn;
        g_topk_e[t * 2 + 1] = i1;  g_topk_p[t * 2 + 1] = p1 * dn;
    }
}

// ---------------- kernel 1: finalize routing + block list + inverse map ----------------
__global__ void __launch_bounds__(1024) finalize_kernel() {
    __shared__ int scnt[ED], soff[ED], sfill[ED];
    int tid = threadIdx.x;
    if (tid < ED) { scnt[tid] = 0; sfill[tid] = 0; }
    __syncthreads();
    for (int j = tid; j < NJOBS; j += 1024) atomicAdd(&scnt[g_topk_e[j]], 1);
    __syncthreads();
    if (tid == 0) {
        int o = 0, nb = 0;
        for (int e = 0; e < ED; e++) {
            soff[e] = o;
            g_off[e] = o;
            g_cnt[e] = scnt[e];
            for (int mm = 0; mm < scnt[e]; mm += 128) {
                g_blk_e[nb] = e;
                g_blk_m[nb] = mm;
                nb++;
            }
            o += scnt[e];
        }
        g_nblk = nb;
    }
    __syncthreads();
    for (int j = tid; j < NJOBS; j += 1024) {
        int e = g_topk_e[j];
        int pos = atomicAdd(&sfill[e], 1);
        int jj = soff[e] + pos;
        g_jobs_tok[jj] = j >> 1;
        g_tok2job[j]   = jj;
    }
}

// ---------------- converts (hi planes only), split for overlap ----------------
#define NX4  ((size_t)TOK * HD / 4)
#define NW4  ((size_t)ED * HD * FD / 4)
__device__ __forceinline__ void cvt4(const float4* src, __half* dst, size_t jj) {
    float4 v = src[jj];
    uint32_t hw[2];
    __half h0 = __float2half_rn(v.x), h1 = __float2half_rn(v.y);
    __half h2 = __float2half_rn(v.z), h3 = __float2half_rn(v.w);
    hw[0] = (uint32_t)__half_as_ushort(h0) | ((uint32_t)__half_as_ushort(h1) << 16);
    hw[1] = (uint32_t)__half_as_ushort(h2) | ((uint32_t)__half_as_ushort(h3) << 16);
    ((uint2*)dst)[jj] = make_uint2(hw[0], hw[1]);
}
__global__ void __launch_bounds__(256) convert_xw1(const float* __restrict__ x,
                                                   const float* __restrict__ W1) {
    size_t i = (size_t)blockIdx.x * 256 + threadIdx.x;
    if (i < NX4) cvt4((const float4*)x, g_xhi, i);
    else if (i < NX4 + NW4) cvt4((const float4*)W1, g_w1hi, i - NX4);
}
__global__ void __launch_bounds__(256) convert_w2(const float* __restrict__ W2) {
    size_t i = (size_t)blockIdx.x * 256 + threadIdx.x;
    if (i < NW4) cvt4((const float4*)W2, g_w2hi, i);
}

// ---------------- 1-pass fp16 grouped GEMM, 128m x 256n x 64k, 512 threads ----------------
// Grid TRANSPOSED for L2 locality: blockIdx.y = block-list (m) index,
// blockIdx.x = n-block (x ksplit) index -> CTAs sharing an A tile are consecutive.
#define STAGES 4
#define STAGE_BYTES 49152
#define SMEM_BYTES (1024 + STAGES * STAGE_BYTES)
#define GTHREADS 512

template <int KDIM, int NDIM, int KSPLIT, bool GATHER, bool DOGELU>
__global__ void __launch_bounds__(GTHREADS, 1)
gemm_mma(const __half* __restrict__ Ahi,  // [rows][KDIM]
         const __half* __restrict__ Whi,  // [E][KDIM][NDIM]
         const float* __restrict__ bias) {
    if ((int)blockIdx.y >= g_nblk) return;
    int e   = g_blk_e[blockIdx.y];
    int m0  = g_blk_m[blockIdx.y];
    int cnt = g_cnt[e];
    int off = g_off[e];
    constexpr int NB = NDIM / 256;
    int ky = blockIdx.x / NB;
    int n0 = (blockIdx.x % NB) * 256;
    constexpr int KSEG = KDIM / KSPLIT;
    int k0g = ky * KSEG;

    extern __shared__ __align__(1024) char smem[];
    uint32_t sb = smem_u32(smem);
    int tid = threadIdx.x, wid = tid >> 5, lane = tid & 31;
    int wm = wid >> 2, wn = wid & 3;   // 4m x 4n warp grid
    int* s_tok = (int*)smem;

    if (GATHER && tid < 128) {
        int r = (m0 + tid < cnt) ? tid : 0;
        s_tok[tid] = g_jobs_tok[off + m0 + r];
    }
    __syncthreads();

    const __half* We_hi = Whi + (size_t)e * KDIM * NDIM + (size_t)k0g * NDIM + n0;
    const float* be = bias + (size_t)e * NDIM;

    // ---- A producer: 2 chunks/thread (r = tid>>3 + q*64; kg = tid&7; 64k per row).
    int akg = tid & 7;
    uint32_t aswz = 16u * (uint32_t)(akg ^ ((tid >> 3) & 7));
    int acol = akg * 8 + k0g;
    const __half* asrc[2];
    uint32_t adst[2];
#pragma unroll
    for (int q = 0; q < 2; q++) {
        int r = (tid >> 3) + q * 64;
        int row;
        if (GATHER) row = s_tok[r];
        else { int rr = (m0 + r < cnt) ? r : 0; row = off + m0 + rr; }
        asrc[q] = Ahi + (size_t)row * KDIM + acol;
        adst[q] = (uint32_t)(r * 128) + aswz;
    }
    // ---- B producer: 4 chunks/thread (kr = tid>>5 + q*16; u = tid&31).
    int bu = tid & 31, bk0 = tid >> 5;
    uint32_t bswz = (uint32_t)((bu >> 3) * 128 + 16 * ((bu & 7) ^ (bk0 & 7)));
    const __half* bsrc_hi = We_hi + (size_t)bk0 * NDIM + bu * 8;

    auto issue = [&](int s, int it) {
        uint32_t base = sb + 1024 + s * STAGE_BYTES;
#pragma unroll
        for (int q = 0; q < 2; q++) cp16(base + adst[q], asrc[q] + it * 64);
        uint32_t bb = base + 16384;
        size_t koff = (size_t)it * 64 * NDIM;
#pragma unroll
        for (int q = 0; q < 4; q++)
            cp16(bb + (uint32_t)((bk0 + q * 16) * 512) + bswz,
                 bsrc_hi + koff + (size_t)(q * 16) * NDIM);
    };

    float acc[16][4];
#pragma unroll
    for (int i = 0; i < 16; i++)
#pragma unroll
        for (int j = 0; j < 4; j++) acc[i][j] = 0.f;

    constexpr int KIT = KSEG / 64;
#pragma unroll
    for (int s = 0; s < STAGES - 1; s++) {
        if (s < KIT) issue(s, s);
        CP_COMMIT();
    }

    int rl = lane & 15, cg = lane >> 4;
    for (int it = 0; it < KIT; it++) {
        CP_WAIT(STAGES - 2);
        __syncthreads();
        uint32_t As = sb + 1024 + (it % STAGES) * STAGE_BYTES;
        uint32_t Bs = As + 16384;
#pragma unroll
        for (int jj = 0; jj < 4; jj++) {
            uint32_t afr[2][4];
#pragma unroll
            for (int mt = 0; mt < 2; mt++) {
                int r = wm * 32 + mt * 16 + rl;
                ldsm_x4(afr[mt], As + r * 128 + 16 * ((jj * 2 + cg) ^ (r & 7)));
            }
            int rB = jj * 16 + rl;
            uint32_t brow = Bs + rB * 512 + wn * 128;
#pragma unroll
            for (int g = 0; g < 4; g++) {
                uint32_t bfr[4];
                ldsm_x4_t(bfr, brow + 16 * ((g * 2 + cg) ^ (rB & 7)));
#pragma unroll
                for (int mt = 0; mt < 2; mt++)
#pragma unroll
                    for (int hh = 0; hh < 2; hh++)
                        mma16816(acc[mt * 8 + g * 2 + hh], afr[mt], &bfr[hh * 2]);
            }
        }
        int nxt = it + STAGES - 1;
        if (nxt < KIT) issue(nxt % STAGES, nxt);
        CP_COMMIT();
    }

    // ---- epilogue ----
#pragma unroll
    for (int mt = 0; mt < 2; mt++) {
#pragma unroll
        for (int nt = 0; nt < 8; nt++) {
            float* d = acc[mt * 8 + nt];
            int nc = n0 + wn * 64 + nt * 8 + 2 * (lane & 3);
            int r0 = m0 + wm * 32 + mt * 16 + (lane >> 2);
            int r1 = r0 + 8;
            if (DOGELU) {
                float b0 = be[nc], b1 = be[nc + 1];
                float c00 = d[0] + b0, c01 = d[1] + b1;
                float c10 = d[2] + b0, c11 = d[3] + b1;
                c00 = 0.5f * c00 * (1.f + erff(c00 * 0.70710678118654752f));
                c01 = 0.5f * c01 * (1.f + erff(c01 * 0.70710678118654752f));
                c10 = 0.5f * c10 * (1.f + erff(c10 * 0.70710678118654752f));
                c11 = 0.5f * c11 * (1.f + erff(c11 * 0.70710678118654752f));
                auto wr = [&](int rr, float a, float b) {
                    size_t base = (size_t)(off + rr) * NDIM + nc;
                    __half h0 = __float2half_rn(a), h1 = __float2half_rn(b);
                    *(uint32_t*)(g_hh + base) =
                        (uint32_t)__half_as_ushort(h0) | ((uint32_t)__half_as_ushort(h1) << 16);
                };
                if (r0 < cnt) wr(r0, c00, c01);
                if (r1 < cnt) wr(r1, c10, c11);
            } else {
                float* ob = g_obuf;
                if (r0 < cnt) *(float2*)(ob + (size_t)(off + r0) * NDIM + nc) = make_float2(d[0], d[1]);
                if (r1 < cnt) *(float2*)(ob + (size_t)(off + r1) * NDIM + nc) = make_float2(d[2], d[3]);
            }
        }
    }
}

// ---------------- combine (token-centric): y = sum_k p_k * LN(o_k + b2 + x) ----------------
__global__ void combine_kernel(const float* __restrict__ x,
                               const float* __restrict__ b2,
                               const float* __restrict__ ln_g,
                               const float* __restrict__ ln_b,
                               float* __restrict__ y) {
    int t = blockIdx.x, tid = threadIdx.x;
    int lane = tid & 31, wid = tid >> 5;
    int j0 = g_tok2job[2 * t], j1 = g_tok2job[2 * t + 1];
    int e0 = g_topk_e[2 * t],  e1 = g_topk_e[2 * t + 1];
    float p0 = g_topk_p[2 * t], p1 = g_topk_p[2 * t + 1];

    const float4* xr  = (const float4*)(x + (size_t)t * HD);
    const float4* a0r = (const float4*)(g_obuf + (size_t)j0 * HD);
    const float4* c0r = (const float4*)(g_obuf + (size_t)j1 * HD);
    const float4* b0r = (const float4*)(b2 + (size_t)e0 * HD);
    const float4* b1r = (const float4*)(b2 + (size_t)e1 * HD);

    float4 xv = xr[tid];
    float4 a0 = a0r[tid], bb0 = b0r[tid];
    float4 c0 = c0r[tid], bb1 = b1r[tid];
    float v0[4] = {a0.x + bb0.x + xv.x, a0.y + bb0.y + xv.y,
                   a0.z + bb0.z + xv.z, a0.w + bb0.w + xv.w};
    float v1[4] = {c0.x + bb1.x + xv.x, c0.y + bb1.y + xv.y,
                   c0.z + bb1.z + xv.z, c0.w + bb1.w + xv.w};

    float s0 = 0.f, q0 = 0.f, s1 = 0.f, q1 = 0.f;
#pragma unroll
    for (int i = 0; i < 4; i++) {
        s0 += v0[i]; q0 += v0[i] * v0[i];
        s1 += v1[i]; q1 += v1[i] * v1[i];
    }
#pragma unroll
    for (int o = 16; o > 0; o >>= 1) {
        s0 += __shfl_xor_sync(0xFFFFFFFFu, s0, o);
        q0 += __shfl_xor_sync(0xFFFFFFFFu, q0, o);
        s1 += __shfl_xor_sync(0xFFFFFFFFu, s1, o);
        q1 += __shfl_xor_sync(0xFFFFFFFFu, q1, o);
    }
    __shared__ float ws[4][8];
    __shared__ float st0, st1, sr0, sr1;
    if (lane == 0) { ws[0][wid] = s0; ws[1][wid] = q0; ws[2][wid] = s1; ws[3][wid] = q1; }
    __syncthreads();
    if (tid == 0) {
        float ts0 = 0.f, tq0 = 0.f, ts1 = 0.f, tq1 = 0.f;
#pragma unroll
        for (int w = 0; w < 8; w++) {
            ts0 += ws[0][w]; tq0 += ws[1][w]; ts1 += ws[2][w]; tq1 += ws[3][w];
        }
        float m0 = ts0 * (1.f / HD), m1 = ts1 * (1.f / HD);
        st0 = m0; st1 = m1;
        sr0 = rsqrtf(tq0 * (1.f / HD) - m0 * m0 + 1e-5f);
        sr1 = rsqrtf(tq1 * (1.f / HD) - m1 * m1 + 1e-5f);
    }
    __syncthreads();
    float m0 = st0, r0 = sr0, m1 = st1, r1 = sr1;

    float out[4];
#pragma unroll
    for (int i = 0; i < 4; i++) {
        int h = tid * 4 + i;
        float o0 = (v0[i] - m0) * r0 * ln_g[(size_t)e0 * HD + h] + ln_b[(size_t)e0 * HD + h];
        float o1 = (v1[i] - m1) * r1 * ln_g[(size_t)e1 * HD + h] + ln_b[(size_t)e1 * HD + h];
        out[i] = o0 * p0 + o1 * p1;
    }
    *(float4*)(y + (size_t)t * HD + tid * 4) = *(float4*)out;
}

// ---------------- launch (multi-stream fork/join, graph-capturable) ----------------
extern "C" void kernel_launch(void* const* d_in, const int* in_sizes, int n_in,
                              void* d_out, int out_size) {
    const float* x      = (const float*)d_in[0];
    const float* W1     = (const float*)d_in[1];
    const float* b1     = (const float*)d_in[2];
    const float* W2     = (const float*)d_in[3];
    const float* b2     = (const float*)d_in[4];
    const float* ln_g   = (const float*)d_in[5];
    const float* ln_b   = (const float*)d_in[6];
    const float* gn_g   = (const float*)d_in[7];
    const float* gn_b   = (const float*)d_in[8];
    const float* gate_w = (const float*)d_in[9];
    const float* gate_b = (const float*)d_in[10];
    float* y = (float*)d_out;

    __half *xhi, *w1hi, *w2hi, *hh;
    cudaGetSymbolAddress((void**)&xhi,  g_xhi);
    cudaGetSymbolAddress((void**)&w1hi, g_w1hi);
    cudaGetSymbolAddress((void**)&w2hi, g_w2hi);
    cudaGetSymbolAddress((void**)&hh,   g_hh);

    cudaFuncSetAttribute(gemm_mma<HD, FD, 1, true, true>,
                         cudaFuncAttributeMaxDynamicSharedMemorySize, SMEM_BYTES);
    cudaFuncSetAttribute(gemm_mma<FD, HD, 1, false, false>,
                         cudaFuncAttributeMaxDynamicSharedMemorySize, SMEM_BYTES);

    // side stream + events (host objects only; no device memory)
    cudaStream_t s1;
    cudaStreamCreateWithFlags(&s1, cudaStreamNonBlocking);
    cudaEvent_t ev0, ev1, ev2;
    cudaEventCreateWithFlags(&ev0, cudaEventDisableTiming);
    cudaEventCreateWithFlags(&ev1, cudaEventDisableTiming);
    cudaEventCreateWithFlags(&ev2, cudaEventDisableTiming);

    // fork: side stream joins the capture graph at the origin
    cudaEventRecord(ev0, 0);
    cudaStreamWaitEvent(s1, ev0, 0);

    // main stream: routing (launch idx 0, 1)
    gate_kernel<<<TOK, 256>>>(x, gn_g, gn_b, gate_w, gate_b);
    finalize_kernel<<<1, 1024>>>();

    // side stream: convert x + W1 (idx 2), concurrent with gate/finalize
    {
        size_t total = NX4 + NW4;
        convert_xw1<<<(unsigned)((total + 255) / 256), 256, 0, s1>>>(x, W1);
    }
    cudaEventRecord(ev1, s1);
    cudaStreamWaitEvent(0, ev1, 0);

    // GEMM1 (idx 3 — ncu slot): h = gelu(x @ W1[e] + b1[e]); K=1024, N=4096
    // grid: (n-blocks, m-block-list) — transposed for A-tile L2 locality
    gemm_mma<HD, FD, 1, true, true>
        <<<dim3(FD / 256, MAXBLK), GTHREADS, SMEM_BYTES>>>(xhi, w1hi, b1);

    // side stream: convert W2 (idx 4), concurrent with GEMM1
    convert_w2<<<(unsigned)((NW4 + 255) / 256), 256, 0, s1>>>(W2);
    cudaEventRecord(ev2, s1);
    cudaStreamWaitEvent(0, ev2, 0);

    // GEMM2 (idx 5): o = h @ W2[e]; K=4096 single-chain, N=1024
    gemm_mma<FD, HD, 1, false, false>
        <<<dim3(HD / 256, MAXBLK), GTHREADS, SMEM_BYTES>>>(hh, w2hi, b2);

    // combine (idx 6): token-centric, plain stores
    combine_kernel<<<TOK, 256>>>(x, b2, ln_g, ln_b, y);
}